// round 2
// baseline (speedup 1.0000x reference)
#include <cuda_runtime.h>

// Problem constants (from reference): N=100000, F=16, E=3200000, H=64
#define NN 100000
#define FF 16
#define EE 3200000
#define HH 64

// Scratch tables, stored as float4 for guaranteed 16B alignment.
// P[n][j] = sum_k x[n][k]*W1[k][j] + b1[j]   (dst half of concat)
// Q[n][j] = sum_k x[n][k]*W1[16+k][j]        (src half of concat)
__device__ float4 g_P4[(size_t)NN * (HH / 4)];
__device__ float4 g_Q4[(size_t)NN * (HH / 4)];

// ---------------------------------------------------------------------------
// Kernel 1: per-node precompute of P and Q. One thread per (node, j).
// ---------------------------------------------------------------------------
__global__ void __launch_bounds__(256)
precompute_kernel(const float* __restrict__ x,
                  const float* __restrict__ W1,
                  const float* __restrict__ b1)
{
    __shared__ float sW1[2 * FF * HH];   // 2048 floats = 8 KB
    __shared__ float sb1[HH];
    for (int i = threadIdx.x; i < 2 * FF * HH; i += blockDim.x) sW1[i] = W1[i];
    if (threadIdx.x < HH) sb1[threadIdx.x] = b1[threadIdx.x];
    __syncthreads();

    int idx = blockIdx.x * blockDim.x + threadIdx.x;
    if (idx >= NN * HH) return;
    int n = idx >> 6;          // node
    int j = idx & 63;          // output column

    const float* xr = x + (size_t)n * FF;
    float p = sb1[j];
    float q = 0.0f;
#pragma unroll
    for (int k = 0; k < FF; k++) {
        float xv = __ldg(xr + k);          // broadcast within warp
        p = fmaf(xv, sW1[k * HH + j], p);
        q = fmaf(xv, sW1[(FF + k) * HH + j], q);
    }
    ((float*)g_P4)[idx] = p;
    ((float*)g_Q4)[idx] = q;
}

// ---------------------------------------------------------------------------
// Kernel 2: per-edge. 4 threads per edge, each owns 16 of the 64 h-lanes.
//   h = relu(P[dst] + Q[src]); a = h.W2[:,0] + b2[0]; b = h.W2[:,1] + b2[1]
//   out[e] = a * (x_dst - b * x_src)          (16 floats)
// edge_index is int32 (JAX default x64-disabled downcasts int64 -> int32).
// ---------------------------------------------------------------------------
__global__ void __launch_bounds__(256)
edge_kernel(const float* __restrict__ x,
            const int* __restrict__ ei,        // [2, E] int32: row0=src, row1=dst
            const float* __restrict__ W2,      // [64,2] row-major
            const float* __restrict__ b2,      // [2]
            float* __restrict__ out)           // [E,16]
{
    __shared__ float sW2a[HH];
    __shared__ float sW2b[HH];
    if (threadIdx.x < HH) {
        sW2a[threadIdx.x] = W2[threadIdx.x * 2 + 0];
        sW2b[threadIdx.x] = W2[threadIdx.x * 2 + 1];
    }
    __syncthreads();

    long long tid = (long long)blockIdx.x * blockDim.x + threadIdx.x;
    long long e   = tid >> 2;
    int sub       = (int)(tid & 3);
    if (e >= EE) return;

    int src = ei[e];
    int dst = ei[(long long)EE + e];

    const float4* Pd = g_P4 + (size_t)dst * (HH / 4) + sub * 4;
    const float4* Qs = g_Q4 + (size_t)src * (HH / 4) + sub * 4;

    float av = 0.0f, bv = 0.0f;
    const int jb = sub * 16;
#pragma unroll
    for (int i = 0; i < 4; i++) {
        float4 p = Pd[i];
        float4 q = Qs[i];
        float h0 = fmaxf(p.x + q.x, 0.0f);
        float h1 = fmaxf(p.y + q.y, 0.0f);
        float h2 = fmaxf(p.z + q.z, 0.0f);
        float h3 = fmaxf(p.w + q.w, 0.0f);
        int j = jb + i * 4;
        av = fmaf(h0, sW2a[j+0], av); av = fmaf(h1, sW2a[j+1], av);
        av = fmaf(h2, sW2a[j+2], av); av = fmaf(h3, sW2a[j+3], av);
        bv = fmaf(h0, sW2b[j+0], bv); bv = fmaf(h1, sW2b[j+1], bv);
        bv = fmaf(h2, sW2b[j+2], bv); bv = fmaf(h3, sW2b[j+3], bv);
    }

    // reduce the two dot products across the 4 lanes of this edge
    av += __shfl_xor_sync(0xffffffffu, av, 1);
    av += __shfl_xor_sync(0xffffffffu, av, 2);
    bv += __shfl_xor_sync(0xffffffffu, bv, 1);
    bv += __shfl_xor_sync(0xffffffffu, bv, 2);
    av += b2[0];
    bv += b2[1];

    // epilogue: each of the 4 threads handles 4 of the 16 output floats
    const float4* xdp = (const float4*)(x + (size_t)dst * FF) + sub;
    const float4* xsp = (const float4*)(x + (size_t)src * FF) + sub;
    float4 xd = *xdp;
    float4 xs = *xsp;
    float4 o;
    o.x = av * (xd.x - bv * xs.x);
    o.y = av * (xd.y - bv * xs.y);
    o.z = av * (xd.z - bv * xs.z);
    o.w = av * (xd.w - bv * xs.w);
    ((float4*)(out + (size_t)e * FF))[sub] = o;
}

// ---------------------------------------------------------------------------
// Launch
// ---------------------------------------------------------------------------
extern "C" void kernel_launch(void* const* d_in, const int* in_sizes, int n_in,
                              void* d_out, int out_size)
{
    const float* x   = (const float*)d_in[0];   // [N,16]
    const int*   ei  = (const int*)d_in[1];     // [2,E] int32
    const float* W1  = (const float*)d_in[2];   // [32,64]
    const float* b1  = (const float*)d_in[3];   // [64]
    const float* W2  = (const float*)d_in[4];   // [64,2]
    const float* b2  = (const float*)d_in[5];   // [2]
    float*       out = (float*)d_out;           // [E,16]

    (void)in_sizes; (void)n_in; (void)out_size;

    {
        int total = NN * HH;
        int threads = 256;
        int blocks = (total + threads - 1) / threads;
        precompute_kernel<<<blocks, threads>>>(x, W1, b1);
    }
    {
        long long total = (long long)EE * 4;
        int threads = 256;
        int blocks = (int)((total + threads - 1) / threads);
        edge_kernel<<<blocks, threads>>>(x, ei, W2, b2, out);
    }
}

// round 3
// speedup vs baseline: 1.8660x; 1.8660x over previous
#include <cuda_runtime.h>
#include <cuda_fp16.h>

// Problem constants (from reference): N=100000, F=16, E=3200000, H=64
#define NN 100000
#define FF 16
#define EE 3200000
#define HH 64

// fp16 scratch tables, one 128-byte row per node (64 halves), 16B-aligned.
// P[n][j] = sum_k x[n][k]*W1[k][j] + b1[j]   (dst half of concat)
// Q[n][j] = sum_k x[n][k]*W1[16+k][j]        (src half of concat)
__device__ uint4 g_Ph[(size_t)NN * (HH / 8)];   // 100000 * 8 uint4 = 12.8 MB
__device__ uint4 g_Qh[(size_t)NN * (HH / 8)];

// ---------------------------------------------------------------------------
// Kernel 1: per-node precompute of P and Q in fp16.
// One thread per (node, j-pair): computes j=2*jp and j=2*jp+1, writes __half2.
// ---------------------------------------------------------------------------
__global__ void __launch_bounds__(256)
precompute_kernel(const float* __restrict__ x,
                  const float* __restrict__ W1,
                  const float* __restrict__ b1)
{
    __shared__ float sW1[2 * FF * HH];   // 2048 floats = 8 KB
    __shared__ float sb1[HH];
    for (int i = threadIdx.x; i < 2 * FF * HH; i += blockDim.x) sW1[i] = W1[i];
    if (threadIdx.x < HH) sb1[threadIdx.x] = b1[threadIdx.x];
    __syncthreads();

    int idx = blockIdx.x * blockDim.x + threadIdx.x;   // over NN * 32
    if (idx >= NN * (HH / 2)) return;
    int n  = idx >> 5;           // node
    int jp = idx & 31;           // half2 column pair
    int j0 = jp * 2;
    int j1 = j0 + 1;

    const float* xr = x + (size_t)n * FF;
    float p0 = sb1[j0], p1 = sb1[j1];
    float q0 = 0.0f,    q1 = 0.0f;
#pragma unroll
    for (int k = 0; k < FF; k++) {
        float xv = __ldg(xr + k);                // broadcast within warp
        p0 = fmaf(xv, sW1[k * HH + j0], p0);
        p1 = fmaf(xv, sW1[k * HH + j1], p1);
        q0 = fmaf(xv, sW1[(FF + k) * HH + j0], q0);
        q1 = fmaf(xv, sW1[(FF + k) * HH + j1], q1);
    }
    ((__half2*)g_Ph)[idx] = __floats2half2_rn(p0, p1);
    ((__half2*)g_Qh)[idx] = __floats2half2_rn(q0, q1);
}

// ---------------------------------------------------------------------------
// Kernel 2: per-edge. 4 threads per edge. Coalesced intra-row ordering:
// at load i, lane sub reads row chunk (i*4+sub)*16B, so the 4 lanes of an
// edge cover one contiguous 64B region per instruction (1 L1 wavefront/edge).
//   h = relu(P[dst] + Q[src]); a = h.W2[:,0]+b2[0]; b = h.W2[:,1]+b2[1]
//   out[e] = a * (x_dst - b * x_src)          (16 floats)
// ---------------------------------------------------------------------------
__global__ void __launch_bounds__(256)
edge_kernel(const float* __restrict__ x,
            const int* __restrict__ ei,        // [2, E] int32: row0=src, row1=dst
            const float* __restrict__ W2,      // [64,2] row-major
            const float* __restrict__ b2,      // [2]
            float* __restrict__ out)           // [E,16]
{
    __shared__ float sW2a[HH];
    __shared__ float sW2b[HH];
    if (threadIdx.x < HH) {
        sW2a[threadIdx.x] = W2[threadIdx.x * 2 + 0];
        sW2b[threadIdx.x] = W2[threadIdx.x * 2 + 1];
    }
    __syncthreads();

    long long tid = (long long)blockIdx.x * blockDim.x + threadIdx.x;
    long long e   = tid >> 2;
    int sub       = (int)(tid & 3);
    if (e >= EE) return;

    int src = ei[e];
    int dst = ei[(long long)EE + e];

    const uint4* Pr = g_Ph + (size_t)dst * (HH / 8);   // 8 uint4 per row
    const uint4* Qr = g_Qh + (size_t)src * (HH / 8);

    float av = 0.0f, bv = 0.0f;
#pragma unroll
    for (int i = 0; i < 2; i++) {
        uint4 pu = Pr[i * 4 + sub];   // 8 halves: j = 32*i + 8*sub + 0..7
        uint4 qu = Qr[i * 4 + sub];
        const __half2* ph = (const __half2*)&pu;
        const __half2* qh = (const __half2*)&qu;
        int jb = 32 * i + 8 * sub;
#pragma unroll
        for (int t = 0; t < 4; t++) {
            float2 p2 = __half22float2(ph[t]);
            float2 q2 = __half22float2(qh[t]);
            float h0 = fmaxf(p2.x + q2.x, 0.0f);
            float h1 = fmaxf(p2.y + q2.y, 0.0f);
            int j = jb + 2 * t;
            av = fmaf(h0, sW2a[j],     av);
            av = fmaf(h1, sW2a[j + 1], av);
            bv = fmaf(h0, sW2b[j],     bv);
            bv = fmaf(h1, sW2b[j + 1], bv);
        }
    }

    // reduce the two dot products across the 4 lanes of this edge
    av += __shfl_xor_sync(0xffffffffu, av, 1);
    av += __shfl_xor_sync(0xffffffffu, av, 2);
    bv += __shfl_xor_sync(0xffffffffu, bv, 1);
    bv += __shfl_xor_sync(0xffffffffu, bv, 2);
    av += b2[0];
    bv += b2[1];

    // epilogue: each of the 4 threads handles 4 of the 16 output floats.
    // x rows are 64B; 4 lanes cover one row contiguously -> 1 wavefront/edge.
    float4 xd = ((const float4*)(x + (size_t)dst * FF))[sub];
    float4 xs = ((const float4*)(x + (size_t)src * FF))[sub];
    float4 o;
    o.x = av * (xd.x - bv * xs.x);
    o.y = av * (xd.y - bv * xs.y);
    o.z = av * (xd.z - bv * xs.z);
    o.w = av * (xd.w - bv * xs.w);
    ((float4*)(out + (size_t)e * FF))[sub] = o;
}

// ---------------------------------------------------------------------------
// Launch
// ---------------------------------------------------------------------------
extern "C" void kernel_launch(void* const* d_in, const int* in_sizes, int n_in,
                              void* d_out, int out_size)
{
    const float* x   = (const float*)d_in[0];   // [N,16]
    const int*   ei  = (const int*)d_in[1];     // [2,E] int32
    const float* W1  = (const float*)d_in[2];   // [32,64]
    const float* b1  = (const float*)d_in[3];   // [64]
    const float* W2  = (const float*)d_in[4];   // [64,2]
    const float* b2  = (const float*)d_in[5];   // [2]
    float*       out = (float*)d_out;           // [E,16]

    (void)in_sizes; (void)n_in; (void)out_size;

    {
        int total = NN * (HH / 2);               // 3.2M threads
        int threads = 256;
        int blocks = (total + threads - 1) / threads;
        precompute_kernel<<<blocks, threads>>>(x, W1, b1);
    }
    {
        long long total = (long long)EE * 4;     // 12.8M threads
        int threads = 256;
        int blocks = (int)((total + threads - 1) / threads);
        edge_kernel<<<blocks, threads>>>(x, ei, W2, b2, out);
    }
}